// round 1
// baseline (speedup 1.0000x reference)
#include <cuda_runtime.h>
#include <math.h>

// Problem constants
#define NE 12
#define NT 4096
#define NH 2048
#define NF 1280

// GEMM tiling
#define BM 64
#define BN 128
#define BK 16

// Scratch (static __device__ globals — allocation-free per harness rules)
__device__ int   g_cnt[NE];
__device__ int   g_tok[NE * NT];
__device__ float g_wgt[NE * NT];
__device__ float g_h[(size_t)NE * NT * NF];   // per (expert,slot) SwiGLU output, combine-weight folded in

// ---------------------------------------------------------------------------
// k_init: zero output (poisoned to 0xAA by harness) and reset expert counters
// ---------------------------------------------------------------------------
__global__ void k_init(float* __restrict__ out, int n4) {
    int i = blockIdx.x * blockDim.x + threadIdx.x;
    if (i < NE) g_cnt[i] = 0;
    if (i < n4) ((float4*)out)[i] = make_float4(0.f, 0.f, 0.f, 0.f);
}

// ---------------------------------------------------------------------------
// k_route: one warp per token. 12 gate dots, top-2 softmax-normalized
// weights, scatter (token, weight) into per-expert slot lists.
// ---------------------------------------------------------------------------
__global__ void k_route(const float* __restrict__ x, const float* __restrict__ gw) {
    int gtid = blockIdx.x * blockDim.x + threadIdx.x;
    int tok  = gtid >> 5;
    int lane = gtid & 31;
    if (tok >= NT) return;

    const float* xr = x + (size_t)tok * NH;
    float acc[NE];
#pragma unroll
    for (int e = 0; e < NE; e++) acc[e] = 0.f;

    for (int i = lane; i < NH; i += 32) {
        float xv = xr[i];
#pragma unroll
        for (int e = 0; e < NE; e++) acc[e] = fmaf(xv, gw[e * NH + i], acc[e]);
    }
#pragma unroll
    for (int e = 0; e < NE; e++) {
#pragma unroll
        for (int o = 16; o > 0; o >>= 1)
            acc[e] += __shfl_xor_sync(0xffffffffu, acc[e], o);
    }

    if (lane == 0) {
        int i1 = 0;
#pragma unroll
        for (int e = 1; e < NE; e++) if (acc[e] > acc[i1]) i1 = e;
        int i2 = (i1 == 0) ? 1 : 0;
#pragma unroll
        for (int e = 0; e < NE; e++) if (e != i1 && acc[e] > acc[i2]) i2 = e;
        // normalized top-2 softmax weights == logistic of logit gap
        float wA = 1.f / (1.f + expf(acc[i2] - acc[i1]));
        float wB = 1.f - wA;
        int p1 = atomicAdd(&g_cnt[i1], 1);
        g_tok[i1 * NT + p1] = tok;  g_wgt[i1 * NT + p1] = wA;
        int p2 = atomicAdd(&g_cnt[i2], 1);
        g_tok[i2 * NT + p2] = tok;  g_wgt[i2 * NT + p2] = wB;
    }
}

// ---------------------------------------------------------------------------
// k_ffn1: per expert, gathered tokens: h = silu(x@w1^T) * (x@w3^T) * cw
// Tile: BM=64 tokens x BN=128 F-cols, K=H=2048 in BK=16 steps.
// 256 threads, each owns a 4x8 sub-tile of BOTH GEMMs (64 accumulators).
// ---------------------------------------------------------------------------
__global__ __launch_bounds__(256) void k_ffn1(
    const float* __restrict__ x,
    const float* __restrict__ w1,
    const float* __restrict__ w3) {
    int e   = blockIdx.z;
    int cnt = g_cnt[e];
    int m0  = blockIdx.y * BM;
    if (m0 >= cnt) return;
    int n0  = blockIdx.x * BN;

    __shared__ float Xs [BK][BM];
    __shared__ float W1s[BK][BN];
    __shared__ float W3s[BK][BN];

    int tid = threadIdx.x;
    int tx = tid & 15, ty = tid >> 4;     // compute mapping: 16x16 threads
    int lr = tid >> 2, lc = tid & 3;      // X loader: row 0..63, float4 0..3
    int wr = tid >> 1, wc = tid & 1;      // W loader: row 0..127, pair 0..1

    int row = m0 + lr;
    int tokenRow = (row < cnt) ? g_tok[e * NT + row] : -1;
    const float* xg  = x + (size_t)((tokenRow >= 0) ? tokenRow : 0) * NH;
    const float* w1g = w1 + ((size_t)e * NF + n0 + wr) * NH;
    const float* w3g = w3 + ((size_t)e * NF + n0 + wr) * NH;

    float acc1[4][8], acc3[4][8];
#pragma unroll
    for (int i = 0; i < 4; i++)
#pragma unroll
        for (int j = 0; j < 8; j++) { acc1[i][j] = 0.f; acc3[i][j] = 0.f; }

    for (int k0 = 0; k0 < NH; k0 += BK) {
        float4 xv = make_float4(0.f, 0.f, 0.f, 0.f);
        if (tokenRow >= 0) xv = *(const float4*)(xg + k0 + lc * 4);
        float4 a1 = *(const float4*)(w1g + k0 + wc * 4);
        float4 b1 = *(const float4*)(w1g + k0 + wc * 4 + 8);
        float4 a3 = *(const float4*)(w3g + k0 + wc * 4);
        float4 b3 = *(const float4*)(w3g + k0 + wc * 4 + 8);

        __syncthreads();
        Xs[lc*4+0][lr] = xv.x; Xs[lc*4+1][lr] = xv.y;
        Xs[lc*4+2][lr] = xv.z; Xs[lc*4+3][lr] = xv.w;
        W1s[wc*4+0][wr] = a1.x; W1s[wc*4+1][wr] = a1.y;
        W1s[wc*4+2][wr] = a1.z; W1s[wc*4+3][wr] = a1.w;
        W1s[wc*4+8][wr] = b1.x; W1s[wc*4+9][wr] = b1.y;
        W1s[wc*4+10][wr] = b1.z; W1s[wc*4+11][wr] = b1.w;
        W3s[wc*4+0][wr] = a3.x; W3s[wc*4+1][wr] = a3.y;
        W3s[wc*4+2][wr] = a3.z; W3s[wc*4+3][wr] = a3.w;
        W3s[wc*4+8][wr] = b3.x; W3s[wc*4+9][wr] = b3.y;
        W3s[wc*4+10][wr] = b3.z; W3s[wc*4+11][wr] = b3.w;
        __syncthreads();

#pragma unroll
        for (int k = 0; k < BK; k++) {
            float4 av = *(const float4*)&Xs[k][ty * 4];
            float4 p  = *(const float4*)&W1s[k][tx * 4];
            float4 q  = *(const float4*)&W1s[k][64 + tx * 4];
            float4 r  = *(const float4*)&W3s[k][tx * 4];
            float4 s  = *(const float4*)&W3s[k][64 + tx * 4];
            float am[4] = {av.x, av.y, av.z, av.w};
            float b1v[8] = {p.x, p.y, p.z, p.w, q.x, q.y, q.z, q.w};
            float b3v[8] = {r.x, r.y, r.z, r.w, s.x, s.y, s.z, s.w};
#pragma unroll
            for (int i = 0; i < 4; i++)
#pragma unroll
                for (int j = 0; j < 8; j++) {
                    acc1[i][j] = fmaf(am[i], b1v[j], acc1[i][j]);
                    acc3[i][j] = fmaf(am[i], b3v[j], acc3[i][j]);
                }
        }
    }

    // Epilogue: SwiGLU + fold combine weight, store h rows (slot-major)
#pragma unroll
    for (int i = 0; i < 4; i++) {
        int mrow = m0 + ty * 4 + i;
        if (mrow < cnt) {
            int slot  = e * NT + mrow;
            float wgt = g_wgt[slot];
            float hv[8];
#pragma unroll
            for (int j = 0; j < 8; j++) {
                float c1 = acc1[i][j], c3 = acc3[i][j];
                float sg = c1 / (1.f + expf(-c1));
                hv[j] = sg * c3 * wgt;
            }
            float* hrow = g_h + (size_t)slot * NF;
            *(float4*)&hrow[n0 + tx * 4]      = make_float4(hv[0], hv[1], hv[2], hv[3]);
            *(float4*)&hrow[n0 + 64 + tx * 4] = make_float4(hv[4], hv[5], hv[6], hv[7]);
        }
    }
}

// ---------------------------------------------------------------------------
// k_ffn2: per expert, out[token] += h_slot @ w2^T   (weight pre-folded)
// Tile: BM=64 slots x BN=128 H-cols, K=F=1280 in BK=16 steps.
// ---------------------------------------------------------------------------
__global__ __launch_bounds__(256) void k_ffn2(
    const float* __restrict__ w2, float* __restrict__ out) {
    int e   = blockIdx.z;
    int cnt = g_cnt[e];
    int m0  = blockIdx.y * BM;
    if (m0 >= cnt) return;
    int n0  = blockIdx.x * BN;

    __shared__ float Hs[BK][BM];
    __shared__ float Ws[BK][BN];

    int tid = threadIdx.x;
    int tx = tid & 15, ty = tid >> 4;
    int lr = tid >> 2, lc = tid & 3;
    int wr = tid >> 1, wc = tid & 1;

    int row = m0 + lr;
    bool valid = (row < cnt);
    const float* hg = g_h + (size_t)(e * NT + row) * NF;
    const float* wg = w2 + ((size_t)e * NH + n0 + wr) * NF;

    float acc[4][8];
#pragma unroll
    for (int i = 0; i < 4; i++)
#pragma unroll
        for (int j = 0; j < 8; j++) acc[i][j] = 0.f;

    for (int k0 = 0; k0 < NF; k0 += BK) {
        float4 hv = make_float4(0.f, 0.f, 0.f, 0.f);
        if (valid) hv = *(const float4*)(hg + k0 + lc * 4);
        float4 a = *(const float4*)(wg + k0 + wc * 4);
        float4 b = *(const float4*)(wg + k0 + wc * 4 + 8);

        __syncthreads();
        Hs[lc*4+0][lr] = hv.x; Hs[lc*4+1][lr] = hv.y;
        Hs[lc*4+2][lr] = hv.z; Hs[lc*4+3][lr] = hv.w;
        Ws[wc*4+0][wr] = a.x; Ws[wc*4+1][wr] = a.y;
        Ws[wc*4+2][wr] = a.z; Ws[wc*4+3][wr] = a.w;
        Ws[wc*4+8][wr] = b.x; Ws[wc*4+9][wr] = b.y;
        Ws[wc*4+10][wr] = b.z; Ws[wc*4+11][wr] = b.w;
        __syncthreads();

#pragma unroll
        for (int k = 0; k < BK; k++) {
            float4 av = *(const float4*)&Hs[k][ty * 4];
            float4 p  = *(const float4*)&Ws[k][tx * 4];
            float4 q  = *(const float4*)&Ws[k][64 + tx * 4];
            float am[4] = {av.x, av.y, av.z, av.w};
            float bv[8] = {p.x, p.y, p.z, p.w, q.x, q.y, q.z, q.w};
#pragma unroll
            for (int i = 0; i < 4; i++)
#pragma unroll
                for (int j = 0; j < 8; j++)
                    acc[i][j] = fmaf(am[i], bv[j], acc[i][j]);
        }
    }

    // Epilogue: scatter-accumulate into out[token]. Each out element receives
    // exactly 2 contributions (top-2) — fp32 add is commutative, so result is
    // deterministic regardless of atomic order.
#pragma unroll
    for (int i = 0; i < 4; i++) {
        int mrow = m0 + ty * 4 + i;
        if (mrow < cnt) {
            int tok = g_tok[e * NT + mrow];
            float* orow = out + (size_t)tok * NH;
#pragma unroll
            for (int j = 0; j < 8; j++) {
                int n = (j < 4) ? (n0 + tx * 4 + j) : (n0 + 64 + tx * 4 + (j - 4));
                atomicAdd(&orow[n], acc[i][j]);
            }
        }
    }
}

// ---------------------------------------------------------------------------
// kernel_launch: init -> route -> FFN1 -> FFN2 (all default stream, ordered)
// ---------------------------------------------------------------------------
extern "C" void kernel_launch(void* const* d_in, const int* in_sizes, int n_in,
                              void* d_out, int out_size) {
    const float* x  = (const float*)d_in[0];  // hidden_states [4,1024,2048]
    const float* gw = (const float*)d_in[1];  // gate_w [12,2048]
    const float* w1 = (const float*)d_in[2];  // w1 [12,1280,2048]
    const float* w2 = (const float*)d_in[3];  // w2 [12,2048,1280]
    const float* w3 = (const float*)d_in[4];  // w3 [12,1280,2048]
    float* out = (float*)d_out;
    (void)in_sizes; (void)n_in;

    int n4 = out_size / 4;  // float4 count
    k_init<<<(n4 + 255) / 256, 256>>>(out, n4);
    k_route<<<(NT * 32 + 127) / 128, 128>>>(x, gw);

    dim3 g1(NF / BN, NT / BM, NE);  // (10, 64, 12) — excess m-tiles early-exit on cnt
    k_ffn1<<<g1, 256>>>(x, w1, w3);

    dim3 g2(NH / BN, NT / BM, NE);  // (16, 64, 12)
    k_ffn2<<<g2, 256>>>(w2, out);
}

// round 3
// speedup vs baseline: 1.9534x; 1.9534x over previous
#include <cuda_runtime.h>
#include <math.h>
#include <stdint.h>

// Problem constants
#define NE 12
#define NT 4096
#define NH 2048
#define NF 1280

// SMEM tile geometry: rows of 32 bf16 data + 8 pad (stride 40 elems = 80B).
// 80B row stride rotates banks by 20 per row -> conflict-free ldmatrix.
#define STR 40
#define ROWB (STR * 2)

// Scratch (static __device__ globals — allocation-free per harness rules)
__device__ int   g_cnt[NE];
__device__ int   g_tok[NE * NT];
__device__ float g_wgt[NE * NT];
__device__ float g_t1[(size_t)NE * NT * NF];  // x @ w1^T
__device__ float g_h [(size_t)NE * NT * NF];  // silu(t1) * (x@w3^T) * cw

// ---------------------------------------------------------------------------
// helpers
// ---------------------------------------------------------------------------
__device__ __forceinline__ uint32_t s2u(const void* p) {
    uint32_t a;
    asm("{ .reg .u64 t; cvta.to.shared.u64 t, %1; cvt.u32.u64 %0, t; }"
        : "=r"(a) : "l"(p));
    return a;
}

__device__ __forceinline__ void ldm4(uint32_t r[4], uint32_t a) {
    asm volatile("ldmatrix.sync.aligned.m8n8.x4.shared.b16 {%0,%1,%2,%3}, [%4];"
                 : "=r"(r[0]), "=r"(r[1]), "=r"(r[2]), "=r"(r[3]) : "r"(a));
}

__device__ __forceinline__ void mma16816(float c[4], const uint32_t a[4],
                                         uint32_t b0, uint32_t b1) {
    asm volatile(
        "mma.sync.aligned.m16n8k16.row.col.f32.bf16.bf16.f32 "
        "{%0,%1,%2,%3},{%4,%5,%6,%7},{%8,%9},{%0,%1,%2,%3};"
        : "+f"(c[0]), "+f"(c[1]), "+f"(c[2]), "+f"(c[3])
        : "r"(a[0]), "r"(a[1]), "r"(a[2]), "r"(a[3]), "r"(b0), "r"(b1));
}

__device__ __forceinline__ uint32_t cvt2bf(float lo, float hi) {
    uint32_t r;
    asm("cvt.rn.bf16x2.f32 %0, %1, %2;" : "=r"(r) : "f"(hi), "f"(lo));
    return r;
}

// hi = truncated-mantissa bf16 (exact), lo = rn(x - hi) as bf16
__device__ __forceinline__ void split4(float4 v, uint2& hi, uint2& lo) {
    uint32_t ax = __float_as_uint(v.x), ay = __float_as_uint(v.y);
    uint32_t az = __float_as_uint(v.z), aw = __float_as_uint(v.w);
    hi.x = __byte_perm(ax, ay, 0x7632);
    hi.y = __byte_perm(az, aw, 0x7632);
    lo.x = cvt2bf(v.x - __uint_as_float(ax & 0xFFFF0000u),
                  v.y - __uint_as_float(ay & 0xFFFF0000u));
    lo.y = cvt2bf(v.z - __uint_as_float(az & 0xFFFF0000u),
                  v.w - __uint_as_float(aw & 0xFFFF0000u));
}

// ---------------------------------------------------------------------------
// k_init / k_route
// ---------------------------------------------------------------------------
__global__ void k_init(float* __restrict__ out, int n4) {
    int i = blockIdx.x * blockDim.x + threadIdx.x;
    if (i < NE) g_cnt[i] = 0;
    if (i < n4) ((float4*)out)[i] = make_float4(0.f, 0.f, 0.f, 0.f);
}

__global__ void k_route(const float* __restrict__ x, const float* __restrict__ gw) {
    int gtid = blockIdx.x * blockDim.x + threadIdx.x;
    int tok = gtid >> 5, lane = gtid & 31;
    if (tok >= NT) return;
    const float* xr = x + (size_t)tok * NH;
    float acc[NE];
#pragma unroll
    for (int e = 0; e < NE; e++) acc[e] = 0.f;
    for (int i = lane; i < NH; i += 32) {
        float xv = xr[i];
#pragma unroll
        for (int e = 0; e < NE; e++) acc[e] = fmaf(xv, gw[e * NH + i], acc[e]);
    }
#pragma unroll
    for (int e = 0; e < NE; e++) {
#pragma unroll
        for (int o = 16; o > 0; o >>= 1)
            acc[e] += __shfl_xor_sync(0xffffffffu, acc[e], o);
    }
    if (lane == 0) {
        int i1 = 0;
#pragma unroll
        for (int e = 1; e < NE; e++) if (acc[e] > acc[i1]) i1 = e;
        int i2 = (i1 == 0) ? 1 : 0;
#pragma unroll
        for (int e = 0; e < NE; e++) if (e != i1 && acc[e] > acc[i2]) i2 = e;
        float wA = 1.f / (1.f + expf(acc[i2] - acc[i1]));
        float wB = 1.f - wA;
        int p1 = atomicAdd(&g_cnt[i1], 1);
        g_tok[i1 * NT + p1] = tok; g_wgt[i1 * NT + p1] = wA;
        int p2 = atomicAdd(&g_cnt[i2], 1);
        g_tok[i2 * NT + p2] = tok; g_wgt[i2 * NT + p2] = wB;
    }
}

// ---------------------------------------------------------------------------
// k_gemm<MODE>: 128x128 CTA tile, mma.sync bf16 3-term split, K-chunks of 32
//   MODE 1: A = gathered x rows, B = w1[e]   -> g_t1
//   MODE 3: A = gathered x rows, B = w3[e]   -> g_h = silu(t1)*c3*cw
//   MODE 2: A = g_h slot rows,   B = w2[e]   -> atomicAdd into out[token]
// ---------------------------------------------------------------------------
struct Smem {
    unsigned long long aptr[128];
    __align__(16) uint16_t Ah[128 * STR];
    __align__(16) uint16_t Al[128 * STR];
    __align__(16) uint16_t Bh[128 * STR];
    __align__(16) uint16_t Bl[128 * STR];
};

template<int MODE>
__global__ __launch_bounds__(256, 1) void k_gemm(
    const float* __restrict__ x, const float* __restrict__ Bw,
    float* __restrict__ outp) {
    constexpr int KD = (MODE == 2) ? NF : NH;
    constexpr int ND = (MODE == 2) ? NH : NF;
    constexpr int NC = KD / 32;

    int e = blockIdx.z;
    int cnt = g_cnt[e];
    int m0 = blockIdx.y * 128;
    if (m0 >= cnt) return;
    int n0 = blockIdx.x * 128;

    __shared__ Smem s;
    int tid = threadIdx.x, lane = tid & 31, wid = tid >> 5;
    int wM = wid >> 2, wN = wid & 3;

    if (tid < 128) {
        int gm = m0 + tid;
        const float* p = 0;
        if (gm < cnt) {
            if (MODE == 2) p = g_h + (size_t)(e * NT + gm) * NF;
            else           p = x + (size_t)g_tok[e * NT + gm] * NH;
        }
        s.aptr[tid] = (unsigned long long)p;
    }
    __syncthreads();

    const float* ap = (const float*)s.aptr[tid >> 1];
    const float* bp = Bw + ((size_t)e * ND + n0 + (tid >> 1)) * KD;
    int f4o = (tid & 1) * 4;     // float4 index within the 32-float row chunk
    int srow = tid >> 1;

    float C[4][4][4];
#pragma unroll
    for (int i = 0; i < 4; i++)
#pragma unroll
        for (int j = 0; j < 4; j++)
#pragma unroll
            for (int q = 0; q < 4; q++) C[i][j][q] = 0.f;

    uint32_t sAh = s2u(s.Ah), sAl = s2u(s.Al), sBh = s2u(s.Bh), sBl = s2u(s.Bl);

    float4 pA[4], pB[4];

    // prefetch + convert chunk 0
    {
        if (ap) {
            const float4* q = (const float4*)ap;
#pragma unroll
            for (int j = 0; j < 4; j++) pA[j] = q[f4o + j];
        } else {
#pragma unroll
            for (int j = 0; j < 4; j++) pA[j] = make_float4(0.f, 0.f, 0.f, 0.f);
        }
        const float4* qb = (const float4*)bp;
#pragma unroll
        for (int j = 0; j < 4; j++) pB[j] = qb[f4o + j];
#pragma unroll
        for (int j = 0; j < 4; j++) {
            uint2 hi, lo;
            uint32_t off = (uint32_t)srow * ROWB + (uint32_t)(f4o + j) * 8;
            split4(pA[j], hi, lo);
            *(uint2*)((char*)s.Ah + off) = hi;
            *(uint2*)((char*)s.Al + off) = lo;
            split4(pB[j], hi, lo);
            *(uint2*)((char*)s.Bh + off) = hi;
            *(uint2*)((char*)s.Bl + off) = lo;
        }
    }
    __syncthreads();

#pragma unroll 1
    for (int c = 0; c < NC; c++) {
        // prefetch next chunk into registers (overlaps with MMA below)
        if (c + 1 < NC) {
            int k0 = (c + 1) * 32;
            if (ap) {
                const float4* q = (const float4*)(ap + k0);
#pragma unroll
                for (int j = 0; j < 4; j++) pA[j] = q[f4o + j];
            } else {
#pragma unroll
                for (int j = 0; j < 4; j++) pA[j] = make_float4(0.f, 0.f, 0.f, 0.f);
            }
            const float4* qb = (const float4*)(bp + k0);
#pragma unroll
            for (int j = 0; j < 4; j++) pB[j] = qb[f4o + j];
        }

        // MMA over current chunk: 2 k16 steps x 3 split terms
#pragma unroll
        for (int kk = 0; kk < 2; kk++) {
            uint32_t kB = kk * 32;
            uint32_t ao = (uint32_t)(wM * 64 + (lane & 15)) * ROWB + (lane >> 4) * 16 + kB;
            uint32_t bo = (uint32_t)(wN * 32 + (lane & 15)) * ROWB + (lane >> 4) * 16 + kB;
            uint32_t ah[4][4], al[4][4], bh[2][4], bl[2][4];
#pragma unroll
            for (int mf = 0; mf < 4; mf++) {
                ldm4(ah[mf], sAh + ao + mf * 16 * ROWB);
                ldm4(al[mf], sAl + ao + mf * 16 * ROWB);
            }
#pragma unroll
            for (int g = 0; g < 2; g++) {
                ldm4(bh[g], sBh + bo + g * 16 * ROWB);
                ldm4(bl[g], sBl + bo + g * 16 * ROWB);
            }
#pragma unroll
            for (int mf = 0; mf < 4; mf++)
#pragma unroll
                for (int nf = 0; nf < 4; nf++) {
                    int g = nf >> 1, o = nf & 1;
                    mma16816(C[mf][nf], ah[mf], bh[g][o], bh[g][o + 2]);
                    mma16816(C[mf][nf], ah[mf], bl[g][o], bl[g][o + 2]);
                    mma16816(C[mf][nf], al[mf], bh[g][o], bh[g][o + 2]);
                }
        }
        __syncthreads();

        // store prefetched chunk into SMEM
        if (c + 1 < NC) {
#pragma unroll
            for (int j = 0; j < 4; j++) {
                uint2 hi, lo;
                uint32_t off = (uint32_t)srow * ROWB + (uint32_t)(f4o + j) * 8;
                split4(pA[j], hi, lo);
                *(uint2*)((char*)s.Ah + off) = hi;
                *(uint2*)((char*)s.Al + off) = lo;
                split4(pB[j], hi, lo);
                *(uint2*)((char*)s.Bh + off) = hi;
                *(uint2*)((char*)s.Bl + off) = lo;
            }
        }
        __syncthreads();
    }

    // Epilogue. C frag (mf,nf): d0,d1 -> (row, col..col+1); d2,d3 -> (row+8, ..)
#pragma unroll
    for (int mf = 0; mf < 4; mf++) {
#pragma unroll
        for (int nf = 0; nf < 4; nf++) {
            int r0 = m0 + wM * 64 + mf * 16 + (lane >> 2);
            int r1 = r0 + 8;
            int cc = n0 + wN * 32 + nf * 8 + (lane & 3) * 2;
#pragma unroll
            for (int half = 0; half < 2; half++) {
                int r = half ? r1 : r0;
                float d0 = C[mf][nf][half * 2 + 0];
                float d1 = C[mf][nf][half * 2 + 1];
                if (r < cnt) {
                    size_t slot = (size_t)(e * NT + r);
                    if (MODE == 1) {
                        float* p = g_t1 + slot * NF + cc;
                        p[0] = d0; p[1] = d1;
                    } else if (MODE == 3) {
                        float wg = g_wgt[e * NT + r];
                        const float* t = g_t1 + slot * NF + cc;
                        float a0 = t[0], a1 = t[1];
                        float* p = g_h + slot * NF + cc;
                        p[0] = a0 / (1.f + expf(-a0)) * d0 * wg;
                        p[1] = a1 / (1.f + expf(-a1)) * d1 * wg;
                    } else {
                        int tok = g_tok[e * NT + r];
                        float* p = outp + (size_t)tok * NH + cc;
                        atomicAdd(p + 0, d0);
                        atomicAdd(p + 1, d1);
                    }
                }
            }
        }
    }
}

// ---------------------------------------------------------------------------
// kernel_launch: init -> route -> gemm1 (w1) -> gemm3 (w3 + SwiGLU) -> gemm2
// ---------------------------------------------------------------------------
extern "C" void kernel_launch(void* const* d_in, const int* in_sizes, int n_in,
                              void* d_out, int out_size) {
    const float* x  = (const float*)d_in[0];
    const float* gw = (const float*)d_in[1];
    const float* w1 = (const float*)d_in[2];
    const float* w2 = (const float*)d_in[3];
    const float* w3 = (const float*)d_in[4];
    float* out = (float*)d_out;
    (void)in_sizes; (void)n_in;

    int n4 = out_size / 4;
    k_init<<<(n4 + 255) / 256, 256>>>(out, n4);
    k_route<<<(NT * 32 + 127) / 128, 128>>>(x, gw);

    dim3 g13(NF / 128, NT / 128, NE);   // (10, 32, 12); excess m-tiles exit on cnt
    k_gemm<1><<<g13, 256>>>(x, w1, nullptr);
    k_gemm<3><<<g13, 256>>>(x, w3, nullptr);

    dim3 g2(NH / 128, NT / 128, NE);    // (16, 32, 12)
    k_gemm<2><<<g2, 256>>>(x, w2, out);
}

// round 4
// speedup vs baseline: 2.0597x; 1.0544x over previous
#include <cuda_runtime.h>
#include <math.h>
#include <stdint.h>

// Problem constants
#define NE 12
#define NT 4096
#define NH 2048
#define NF 1280

// GEMM geometry: CTA 128x128, K-chunk 32, SMEM rows 32 bf16 + 8 pad = 80B
#define CH 32
#define ROWB 80
#define TILEB (128 * ROWB)          // 10240 B per plane
#define STG1 (6 * TILEB)            // ffn1 stage: Ah,Al,B1h,B1l,B3h,B3l
#define STG2 (4 * TILEB)            // ffn2 stage: Ah,Al,Bh,Bl
#define SMEM1 (1024 + 3 * STG1)     // 3-stage pipeline + token list
#define SMEM2 (2 * STG2)            // 2-stage, 2 CTAs/SM

// Scratch (static __device__ globals — allocation-free per harness rules)
__device__ int   g_cnt[NE];
__device__ int   g_tok[NE * NT];
__device__ float g_wgt[NE * NT];
__device__ __align__(16) uint16_t g_w1h[(size_t)NE * NF * NH];
__device__ __align__(16) uint16_t g_w1l[(size_t)NE * NF * NH];
__device__ __align__(16) uint16_t g_w3h[(size_t)NE * NF * NH];
__device__ __align__(16) uint16_t g_w3l[(size_t)NE * NF * NH];
__device__ __align__(16) uint16_t g_w2h[(size_t)NE * NH * NF];
__device__ __align__(16) uint16_t g_w2l[(size_t)NE * NH * NF];
__device__ __align__(16) uint16_t g_xh[(size_t)NT * NH];
__device__ __align__(16) uint16_t g_xl[(size_t)NT * NH];
__device__ __align__(16) uint16_t g_hh[(size_t)NE * NT * NF];
__device__ __align__(16) uint16_t g_hl[(size_t)NE * NT * NF];

// ---------------------------------------------------------------------------
// helpers
// ---------------------------------------------------------------------------
__device__ __forceinline__ uint32_t s2u(const void* p) {
    uint32_t a;
    asm("{ .reg .u64 t; cvta.to.shared.u64 t, %1; cvt.u32.u64 %0, t; }"
        : "=r"(a) : "l"(p));
    return a;
}

__device__ __forceinline__ void ldm4(uint32_t r[4], uint32_t a) {
    asm volatile("ldmatrix.sync.aligned.m8n8.x4.shared.b16 {%0,%1,%2,%3}, [%4];"
                 : "=r"(r[0]), "=r"(r[1]), "=r"(r[2]), "=r"(r[3]) : "r"(a));
}

__device__ __forceinline__ void mma16816(float c[4], const uint32_t a[4],
                                         uint32_t b0, uint32_t b1) {
    asm volatile(
        "mma.sync.aligned.m16n8k16.row.col.f32.bf16.bf16.f32 "
        "{%0,%1,%2,%3},{%4,%5,%6,%7},{%8,%9},{%0,%1,%2,%3};"
        : "+f"(c[0]), "+f"(c[1]), "+f"(c[2]), "+f"(c[3])
        : "r"(a[0]), "r"(a[1]), "r"(a[2]), "r"(a[3]), "r"(b0), "r"(b1));
}

__device__ __forceinline__ uint32_t cvt2bf(float lo, float hi) {
    uint32_t r;
    asm("cvt.rn.bf16x2.f32 %0, %1, %2;" : "=r"(r) : "f"(hi), "f"(lo));
    return r;
}

// hi = truncated-mantissa bf16 (exact), lo = rn(x - hi)
__device__ __forceinline__ void split4(float4 v, uint2& hi, uint2& lo) {
    uint32_t ax = __float_as_uint(v.x), ay = __float_as_uint(v.y);
    uint32_t az = __float_as_uint(v.z), aw = __float_as_uint(v.w);
    hi.x = __byte_perm(ax, ay, 0x7632);
    hi.y = __byte_perm(az, aw, 0x7632);
    lo.x = cvt2bf(v.x - __uint_as_float(ax & 0xFFFF0000u),
                  v.y - __uint_as_float(ay & 0xFFFF0000u));
    lo.y = cvt2bf(v.z - __uint_as_float(az & 0xFFFF0000u),
                  v.w - __uint_as_float(aw & 0xFFFF0000u));
}

__device__ __forceinline__ void cpa16(uint32_t dst, const void* src) {
    asm volatile("cp.async.cg.shared.global [%0], [%1], 16;" :: "r"(dst), "l"(src));
}
#define CP_COMMIT() asm volatile("cp.async.commit_group;" ::: "memory")
#define CP_WAIT(n)  asm volatile("cp.async.wait_group %0;" :: "n"(n) : "memory")

// ---------------------------------------------------------------------------
// k_init / k_split / k_route
// ---------------------------------------------------------------------------
__global__ void k_init(float* __restrict__ out, int n4) {
    int i = blockIdx.x * blockDim.x + threadIdx.x;
    if (i < NE) g_cnt[i] = 0;
    if (i < n4) ((float4*)out)[i] = make_float4(0.f, 0.f, 0.f, 0.f);
}

// W: 0=w1, 1=w3, 2=w2, 3=x
template<int W>
__global__ void k_split(const float4* __restrict__ src, int n4) {
    uint2 *dh, *dl;
    if (W == 0)      { dh = (uint2*)g_w1h; dl = (uint2*)g_w1l; }
    else if (W == 1) { dh = (uint2*)g_w3h; dl = (uint2*)g_w3l; }
    else if (W == 2) { dh = (uint2*)g_w2h; dl = (uint2*)g_w2l; }
    else             { dh = (uint2*)g_xh;  dl = (uint2*)g_xl;  }
    int i = blockIdx.x * blockDim.x + threadIdx.x;
    if (i < n4) {
        uint2 h, l;
        split4(src[i], h, l);
        dh[i] = h; dl[i] = l;
    }
}

__global__ void k_route(const float* __restrict__ x, const float* __restrict__ gw) {
    int gtid = blockIdx.x * blockDim.x + threadIdx.x;
    int tok = gtid >> 5, lane = gtid & 31;
    if (tok >= NT) return;
    const float* xr = x + (size_t)tok * NH;
    float acc[NE];
#pragma unroll
    for (int e = 0; e < NE; e++) acc[e] = 0.f;
    for (int i = lane; i < NH; i += 32) {
        float xv = xr[i];
#pragma unroll
        for (int e = 0; e < NE; e++) acc[e] = fmaf(xv, gw[e * NH + i], acc[e]);
    }
#pragma unroll
    for (int e = 0; e < NE; e++) {
#pragma unroll
        for (int o = 16; o > 0; o >>= 1)
            acc[e] += __shfl_xor_sync(0xffffffffu, acc[e], o);
    }
    if (lane == 0) {
        int i1 = 0;
#pragma unroll
        for (int e = 1; e < NE; e++) if (acc[e] > acc[i1]) i1 = e;
        int i2 = (i1 == 0) ? 1 : 0;
#pragma unroll
        for (int e = 0; e < NE; e++) if (e != i1 && acc[e] > acc[i2]) i2 = e;
        float wA = 1.f / (1.f + expf(acc[i2] - acc[i1]));
        float wB = 1.f - wA;
        int p1 = atomicAdd(&g_cnt[i1], 1);
        g_tok[i1 * NT + p1] = tok; g_wgt[i1 * NT + p1] = wA;
        int p2 = atomicAdd(&g_cnt[i2], 1);
        g_tok[i2 * NT + p2] = tok; g_wgt[i2 * NT + p2] = wB;
    }
}

// ---------------------------------------------------------------------------
// k_ffn1: fused x@w1^T and x@w3^T + SwiGLU epilogue -> hi/lo h planes.
// 3-stage cp.async pipeline, 8 warps (2M x 4N), warp tile 64x32.
// ---------------------------------------------------------------------------
__global__ __launch_bounds__(256, 1) void k_ffn1() {
    int e = blockIdx.z;
    int cnt = g_cnt[e];
    int m0 = blockIdx.y * 128;
    if (m0 >= cnt) return;
    int n0 = blockIdx.x * 128;

    extern __shared__ char sm[];
    int* stok = (int*)sm;
    uint32_t su = s2u(sm);
    int tid = threadIdx.x, lane = tid & 31, wid = tid >> 5;
    int wM = wid >> 2, wN = wid & 3;

    if (tid < 128) {
        int r = m0 + tid;
        if (r >= cnt) r = cnt - 1;
        stok[tid] = g_tok[e * NT + r];
    }
    __syncthreads();

    const size_t wb = ((size_t)e * NF + n0) * NH;

    float C1[4][4][4], C3[4][4][4];
#pragma unroll
    for (int i = 0; i < 4; i++)
#pragma unroll
        for (int j = 0; j < 4; j++)
#pragma unroll
            for (int q = 0; q < 4; q++) { C1[i][j][q] = 0.f; C3[i][j][q] = 0.f; }

    auto issue = [&](int c) {
        int k0 = c * CH;
        uint32_t sb = su + 1024 + (c % 3) * STG1;
#pragma unroll
        for (int it = 0; it < 2; it++) {
            int i = tid + it * 256;
            int r = i >> 2, ch = i & 3;
            uint32_t d = sb + r * ROWB + ch * 16;
            size_t ga = (size_t)stok[r] * NH + k0 + ch * 8;
            cpa16(d,             g_xh + ga);
            cpa16(d + TILEB,     g_xl + ga);
            size_t gb = wb + (size_t)r * NH + k0 + ch * 8;
            cpa16(d + 2 * TILEB, g_w1h + gb);
            cpa16(d + 3 * TILEB, g_w1l + gb);
            cpa16(d + 4 * TILEB, g_w3h + gb);
            cpa16(d + 5 * TILEB, g_w3l + gb);
        }
        CP_COMMIT();
    };

    constexpr int NC = NH / CH;   // 64
    issue(0);
    issue(1);

#pragma unroll 1
    for (int c = 0; c < NC; c++) {
        if (c + 2 < NC) { issue(c + 2); CP_WAIT(2); }
        else if (c + 1 < NC) CP_WAIT(1);
        else CP_WAIT(0);
        __syncthreads();

        uint32_t sb = su + 1024 + (c % 3) * STG1;
#pragma unroll
        for (int kk = 0; kk < 2; kk++) {
            uint32_t ao = sb + (wM * 64 + (lane & 15)) * ROWB + (lane >> 4) * 16 + kk * 32;
            uint32_t bo = sb + 2 * TILEB + (wN * 32 + (lane & 15)) * ROWB + (lane >> 4) * 16 + kk * 32;
            uint32_t ah[4][4], al[4][4];
#pragma unroll
            for (int mf = 0; mf < 4; mf++) {
                ldm4(ah[mf], ao + mf * 16 * ROWB);
                ldm4(al[mf], ao + TILEB + mf * 16 * ROWB);
            }
            {   // w1 terms
                uint32_t bh[2][4], bl[2][4];
#pragma unroll
                for (int g = 0; g < 2; g++) {
                    ldm4(bh[g], bo + g * 16 * ROWB);
                    ldm4(bl[g], bo + TILEB + g * 16 * ROWB);
                }
#pragma unroll
                for (int mf = 0; mf < 4; mf++)
#pragma unroll
                    for (int nf = 0; nf < 4; nf++) {
                        int g = nf >> 1, o = nf & 1;
                        mma16816(C1[mf][nf], ah[mf], bh[g][o], bh[g][o + 2]);
                        mma16816(C1[mf][nf], ah[mf], bl[g][o], bl[g][o + 2]);
                        mma16816(C1[mf][nf], al[mf], bh[g][o], bh[g][o + 2]);
                    }
            }
            {   // w3 terms (reuse A frags)
                uint32_t bh[2][4], bl[2][4];
#pragma unroll
                for (int g = 0; g < 2; g++) {
                    ldm4(bh[g], bo + 2 * TILEB + g * 16 * ROWB);
                    ldm4(bl[g], bo + 3 * TILEB + g * 16 * ROWB);
                }
#pragma unroll
                for (int mf = 0; mf < 4; mf++)
#pragma unroll
                    for (int nf = 0; nf < 4; nf++) {
                        int g = nf >> 1, o = nf & 1;
                        mma16816(C3[mf][nf], ah[mf], bh[g][o], bh[g][o + 2]);
                        mma16816(C3[mf][nf], ah[mf], bl[g][o], bl[g][o + 2]);
                        mma16816(C3[mf][nf], al[mf], bh[g][o], bh[g][o + 2]);
                    }
            }
        }
        __syncthreads();
    }

    // Epilogue: h = silu(c1)*c3*wgt, emitted pre-split (hi/lo bf16 planes)
#pragma unroll
    for (int mf = 0; mf < 4; mf++)
#pragma unroll
        for (int nf = 0; nf < 4; nf++) {
            int rb = m0 + wM * 64 + mf * 16 + (lane >> 2);
            int cc = n0 + wN * 32 + nf * 8 + (lane & 3) * 2;
#pragma unroll
            for (int hf = 0; hf < 2; hf++) {
                int r = rb + hf * 8;
                if (r < cnt) {
                    float wg = g_wgt[e * NT + r];
                    float a0 = C1[mf][nf][hf * 2], a1 = C1[mf][nf][hf * 2 + 1];
                    float h0 = a0 / (1.f + expf(-a0)) * C3[mf][nf][hf * 2] * wg;
                    float h1 = a1 / (1.f + expf(-a1)) * C3[mf][nf][hf * 2 + 1] * wg;
                    size_t off = (size_t)(e * NT + r) * NF + cc;
                    uint32_t b0 = __float_as_uint(h0), b1 = __float_as_uint(h1);
                    *(uint32_t*)(g_hh + off) = __byte_perm(b0, b1, 0x7632);
                    float l0 = h0 - __uint_as_float(b0 & 0xFFFF0000u);
                    float l1 = h1 - __uint_as_float(b1 & 0xFFFF0000u);
                    *(uint32_t*)(g_hl + off) = cvt2bf(l0, l1);
                }
            }
        }
}

// ---------------------------------------------------------------------------
// k_ffn2: out[token] += h @ w2^T, 2-stage pipeline, 2 CTAs/SM.
// ---------------------------------------------------------------------------
__global__ __launch_bounds__(256, 2) void k_ffn2(float* __restrict__ out) {
    int e = blockIdx.z;
    int cnt = g_cnt[e];
    int m0 = blockIdx.y * 128;
    if (m0 >= cnt) return;
    int n0 = blockIdx.x * 128;

    extern __shared__ char sm[];
    uint32_t su = s2u(sm);
    int tid = threadIdx.x, lane = tid & 31, wid = tid >> 5;
    int wM = wid >> 2, wN = wid & 3;

    const size_t wb = ((size_t)e * NH + n0) * NF;

    float C[4][4][4];
#pragma unroll
    for (int i = 0; i < 4; i++)
#pragma unroll
        for (int j = 0; j < 4; j++)
#pragma unroll
            for (int q = 0; q < 4; q++) C[i][j][q] = 0.f;

    auto issue = [&](int c) {
        int k0 = c * CH;
        uint32_t sb = su + (c & 1) * STG2;
#pragma unroll
        for (int it = 0; it < 2; it++) {
            int i = tid + it * 256;
            int r = i >> 2, ch = i & 3;
            int ar = m0 + r;
            if (ar >= cnt) ar = cnt - 1;
            uint32_t d = sb + r * ROWB + ch * 16;
            size_t ga = (size_t)(e * NT + ar) * NF + k0 + ch * 8;
            cpa16(d,             g_hh + ga);
            cpa16(d + TILEB,     g_hl + ga);
            size_t gb = wb + (size_t)r * NF + k0 + ch * 8;
            cpa16(d + 2 * TILEB, g_w2h + gb);
            cpa16(d + 3 * TILEB, g_w2l + gb);
        }
        CP_COMMIT();
    };

    constexpr int NC = NF / CH;   // 40
    issue(0);

#pragma unroll 1
    for (int c = 0; c < NC; c++) {
        if (c + 1 < NC) { issue(c + 1); CP_WAIT(1); }
        else CP_WAIT(0);
        __syncthreads();

        uint32_t sb = su + (c & 1) * STG2;
#pragma unroll
        for (int kk = 0; kk < 2; kk++) {
            uint32_t ao = sb + (wM * 64 + (lane & 15)) * ROWB + (lane >> 4) * 16 + kk * 32;
            uint32_t bo = sb + 2 * TILEB + (wN * 32 + (lane & 15)) * ROWB + (lane >> 4) * 16 + kk * 32;
            uint32_t ah[4][4], al[4][4], bh[2][4], bl[2][4];
#pragma unroll
            for (int mf = 0; mf < 4; mf++) {
                ldm4(ah[mf], ao + mf * 16 * ROWB);
                ldm4(al[mf], ao + TILEB + mf * 16 * ROWB);
            }
#pragma unroll
            for (int g = 0; g < 2; g++) {
                ldm4(bh[g], bo + g * 16 * ROWB);
                ldm4(bl[g], bo + TILEB + g * 16 * ROWB);
            }
#pragma unroll
            for (int mf = 0; mf < 4; mf++)
#pragma unroll
                for (int nf = 0; nf < 4; nf++) {
                    int g = nf >> 1, o = nf & 1;
                    mma16816(C[mf][nf], ah[mf], bh[g][o], bh[g][o + 2]);
                    mma16816(C[mf][nf], ah[mf], bl[g][o], bl[g][o + 2]);
                    mma16816(C[mf][nf], al[mf], bh[g][o], bh[g][o + 2]);
                }
        }
        __syncthreads();
    }

    // Epilogue: scatter-accumulate (2 commutative fp32 adds/elem -> deterministic)
#pragma unroll
    for (int mf = 0; mf < 4; mf++)
#pragma unroll
        for (int nf = 0; nf < 4; nf++) {
            int rb = m0 + wM * 64 + mf * 16 + (lane >> 2);
            int cc = n0 + wN * 32 + nf * 8 + (lane & 3) * 2;
#pragma unroll
            for (int hf = 0; hf < 2; hf++) {
                int r = rb + hf * 8;
                if (r < cnt) {
                    int tok = g_tok[e * NT + r];
                    float* p = out + (size_t)tok * NH + cc;
                    atomicAdd(p + 0, C[mf][nf][hf * 2 + 0]);
                    atomicAdd(p + 1, C[mf][nf][hf * 2 + 1]);
                }
            }
        }
}

// ---------------------------------------------------------------------------
// kernel_launch
// ---------------------------------------------------------------------------
extern "C" void kernel_launch(void* const* d_in, const int* in_sizes, int n_in,
                              void* d_out, int out_size) {
    const float* x  = (const float*)d_in[0];
    const float* gw = (const float*)d_in[1];
    const float* w1 = (const float*)d_in[2];
    const float* w2 = (const float*)d_in[3];
    const float* w3 = (const float*)d_in[4];
    float* out = (float*)d_out;
    (void)in_sizes; (void)n_in;

    static bool attr_set = false;
    if (!attr_set) {
        cudaFuncSetAttribute(k_ffn1, cudaFuncAttributeMaxDynamicSharedMemorySize, SMEM1);
        cudaFuncSetAttribute(k_ffn2, cudaFuncAttributeMaxDynamicSharedMemorySize, SMEM2);
        attr_set = true;
    }

    int n4 = out_size / 4;
    k_init<<<(n4 + 255) / 256, 256>>>(out, n4);

    int nw4 = NE * NF * NH / 4;     // 7,864,320
    int nx4 = NT * NH / 4;          // 2,097,152
    k_split<0><<<(nw4 + 255) / 256, 256>>>((const float4*)w1, nw4);
    k_split<1><<<(nw4 + 255) / 256, 256>>>((const float4*)w3, nw4);
    k_split<2><<<(nw4 + 255) / 256, 256>>>((const float4*)w2, nw4);
    k_split<3><<<(nx4 + 255) / 256, 256>>>((const float4*)x, nx4);

    k_route<<<(NT * 32 + 127) / 128, 128>>>(x, gw);

    dim3 g1(NF / 128, NT / 128, NE);   // (10, 32, 12)
    k_ffn1<<<g1, 256, SMEM1>>>();

    dim3 g2(NH / 128, NT / 128, NE);   // (16, 32, 12)
    k_ffn2<<<g2, 256, SMEM2>>>(out);
}

// round 5
// speedup vs baseline: 2.1513x; 1.0445x over previous
#include <cuda_runtime.h>
#include <math.h>
#include <stdint.h>

// Problem constants
#define NE 12
#define NT 4096
#define NH 2048
#define NF 1280

// GEMM geometry: CTA 64x128, K-chunk 32, SMEM rows 32 bf16 + 8 pad = 80B
#define CH 32
#define ROWB 80
#define APL (64 * ROWB)              // 5120 B  A plane (64 rows)
#define BPL (128 * ROWB)             // 10240 B B plane (128 rows)
#define STG1 (2 * APL + 4 * BPL)     // 51200: Ah,Al,B1h,B1l,B3h,B3l
#define STG2 (2 * APL + 2 * BPL)     // 30720: Ah,Al,Bh,Bl
#define SMEM1 (1024 + 2 * STG1)      // 103424 -> 2 CTAs/SM
#define SMEM2 (2 * STG2)             // 61440  -> 2 CTAs/SM

// Scratch (static __device__ globals — allocation-free per harness rules)
__device__ int   g_cnt[NE];
__device__ int   g_tok[NE * NT];
__device__ float g_wgt[NE * NT];
__device__ __align__(16) uint16_t g_w1h[(size_t)NE * NF * NH];
__device__ __align__(16) uint16_t g_w1l[(size_t)NE * NF * NH];
__device__ __align__(16) uint16_t g_w3h[(size_t)NE * NF * NH];
__device__ __align__(16) uint16_t g_w3l[(size_t)NE * NF * NH];
__device__ __align__(16) uint16_t g_w2h[(size_t)NE * NH * NF];
__device__ __align__(16) uint16_t g_w2l[(size_t)NE * NH * NF];
__device__ __align__(16) uint16_t g_xh[(size_t)NT * NH];
__device__ __align__(16) uint16_t g_xl[(size_t)NT * NH];
__device__ __align__(16) uint16_t g_hh[(size_t)NE * NT * NF];
__device__ __align__(16) uint16_t g_hl[(size_t)NE * NT * NF];

// ---------------------------------------------------------------------------
// helpers
// ---------------------------------------------------------------------------
__device__ __forceinline__ uint32_t s2u(const void* p) {
    uint32_t a;
    asm("{ .reg .u64 t; cvta.to.shared.u64 t, %1; cvt.u32.u64 %0, t; }"
        : "=r"(a) : "l"(p));
    return a;
}

__device__ __forceinline__ void ldm4(uint32_t r[4], uint32_t a) {
    asm volatile("ldmatrix.sync.aligned.m8n8.x4.shared.b16 {%0,%1,%2,%3}, [%4];"
                 : "=r"(r[0]), "=r"(r[1]), "=r"(r[2]), "=r"(r[3]) : "r"(a));
}

__device__ __forceinline__ void mma16816(float c[4], const uint32_t a[4],
                                         uint32_t b0, uint32_t b1) {
    asm volatile(
        "mma.sync.aligned.m16n8k16.row.col.f32.bf16.bf16.f32 "
        "{%0,%1,%2,%3},{%4,%5,%6,%7},{%8,%9},{%0,%1,%2,%3};"
        : "+f"(c[0]), "+f"(c[1]), "+f"(c[2]), "+f"(c[3])
        : "r"(a[0]), "r"(a[1]), "r"(a[2]), "r"(a[3]), "r"(b0), "r"(b1));
}

__device__ __forceinline__ uint32_t cvt2bf(float lo, float hi) {
    uint32_t r;
    asm("cvt.rn.bf16x2.f32 %0, %1, %2;" : "=r"(r) : "f"(hi), "f"(lo));
    return r;
}

// hi = truncated-mantissa bf16 (exact), lo = rn(x - hi)
__device__ __forceinline__ void split4(float4 v, uint2& hi, uint2& lo) {
    uint32_t ax = __float_as_uint(v.x), ay = __float_as_uint(v.y);
    uint32_t az = __float_as_uint(v.z), aw = __float_as_uint(v.w);
    hi.x = __byte_perm(ax, ay, 0x7632);
    hi.y = __byte_perm(az, aw, 0x7632);
    lo.x = cvt2bf(v.x - __uint_as_float(ax & 0xFFFF0000u),
                  v.y - __uint_as_float(ay & 0xFFFF0000u));
    lo.y = cvt2bf(v.z - __uint_as_float(az & 0xFFFF0000u),
                  v.w - __uint_as_float(aw & 0xFFFF0000u));
}

__device__ __forceinline__ void cpa16(uint32_t dst, const void* src) {
    asm volatile("cp.async.cg.shared.global [%0], [%1], 16;" :: "r"(dst), "l"(src));
}
#define CP_COMMIT() asm volatile("cp.async.commit_group;" ::: "memory")
#define CP_WAIT(n)  asm volatile("cp.async.wait_group %0;" :: "n"(n) : "memory")

// ---------------------------------------------------------------------------
// k_init / k_split / k_route
// ---------------------------------------------------------------------------
__global__ void k_init(float* __restrict__ out, int n4) {
    int i = blockIdx.x * blockDim.x + threadIdx.x;
    if (i < NE) g_cnt[i] = 0;
    if (i < n4) ((float4*)out)[i] = make_float4(0.f, 0.f, 0.f, 0.f);
}

template<int W>
__global__ void k_split(const float4* __restrict__ src, int n4) {
    uint2 *dh, *dl;
    if (W == 0)      { dh = (uint2*)g_w1h; dl = (uint2*)g_w1l; }
    else if (W == 1) { dh = (uint2*)g_w3h; dl = (uint2*)g_w3l; }
    else if (W == 2) { dh = (uint2*)g_w2h; dl = (uint2*)g_w2l; }
    else             { dh = (uint2*)g_xh;  dl = (uint2*)g_xl;  }
    int i = blockIdx.x * blockDim.x + threadIdx.x;
    if (i < n4) {
        uint2 h, l;
        split4(src[i], h, l);
        dh[i] = h; dl[i] = l;
    }
}

__global__ void k_route(const float* __restrict__ x, const float* __restrict__ gw) {
    int gtid = blockIdx.x * blockDim.x + threadIdx.x;
    int tok = gtid >> 5, lane = gtid & 31;
    if (tok >= NT) return;
    const float* xr = x + (size_t)tok * NH;
    float acc[NE];
#pragma unroll
    for (int e = 0; e < NE; e++) acc[e] = 0.f;
    for (int i = lane; i < NH; i += 32) {
        float xv = xr[i];
#pragma unroll
        for (int e = 0; e < NE; e++) acc[e] = fmaf(xv, gw[e * NH + i], acc[e]);
    }
#pragma unroll
    for (int e = 0; e < NE; e++) {
#pragma unroll
        for (int o = 16; o > 0; o >>= 1)
            acc[e] += __shfl_xor_sync(0xffffffffu, acc[e], o);
    }
    if (lane == 0) {
        int i1 = 0;
#pragma unroll
        for (int e = 1; e < NE; e++) if (acc[e] > acc[i1]) i1 = e;
        int i2 = (i1 == 0) ? 1 : 0;
#pragma unroll
        for (int e = 0; e < NE; e++) if (e != i1 && acc[e] > acc[i2]) i2 = e;
        float wA = 1.f / (1.f + expf(acc[i2] - acc[i1]));
        float wB = 1.f - wA;
        int p1 = atomicAdd(&g_cnt[i1], 1);
        g_tok[i1 * NT + p1] = tok; g_wgt[i1 * NT + p1] = wA;
        int p2 = atomicAdd(&g_cnt[i2], 1);
        g_tok[i2 * NT + p2] = tok; g_wgt[i2 * NT + p2] = wB;
    }
}

// ---------------------------------------------------------------------------
// k_ffn1: fused x@w1^T, x@w3^T + SwiGLU -> hi/lo h planes.
// CTA 64x128, warps 2x4 (tile 32x32), 2-stage cp.async, 2 CTAs/SM.
// ---------------------------------------------------------------------------
__global__ __launch_bounds__(256, 2) void k_ffn1() {
    int e = blockIdx.z;
    int cnt = g_cnt[e];
    int m0 = blockIdx.y * 64;
    if (m0 >= cnt) return;
    int n0 = blockIdx.x * 128;

    extern __shared__ char sm[];
    int* stok = (int*)sm;
    uint32_t su = s2u(sm);
    int tid = threadIdx.x, lane = tid & 31, wid = tid >> 5;
    int wM = wid >> 2, wN = wid & 3;

    if (tid < 64) {
        int r = m0 + tid;
        if (r >= cnt) r = cnt - 1;
        stok[tid] = g_tok[e * NT + r];
    }
    __syncthreads();

    const size_t wb = ((size_t)e * NF + n0) * NH;

    // per-thread fixed loader roles
    int ap_ = tid & 1, ach = (tid >> 1) & 3, ar0 = tid >> 3;        // A: r = ar0 + 32j
    int bpl = tid & 3, bch = (tid >> 2) & 3, br0 = tid >> 4;        // B: r = br0 + 16j
    const uint16_t* asrc = (ap_ ? g_xl : g_xh);
    const uint16_t* bsrc0 = (bpl == 0) ? g_w1h : (bpl == 1) ? g_w1l : (bpl == 2) ? g_w3h : g_w3l;
    uint32_t adst0 = 1024 + ap_ * APL + ar0 * ROWB + ach * 16;
    uint32_t bdst0 = 1024 + 2 * APL + bpl * BPL + br0 * ROWB + bch * 16;

    float C1[2][4][4], C3[2][4][4];
#pragma unroll
    for (int i = 0; i < 2; i++)
#pragma unroll
        for (int j = 0; j < 4; j++)
#pragma unroll
            for (int q = 0; q < 4; q++) { C1[i][j][q] = 0.f; C3[i][j][q] = 0.f; }

    auto issue = [&](int c) {
        int k0 = c * CH;
        uint32_t sb = su + (c & 1) * STG1;
#pragma unroll
        for (int j = 0; j < 2; j++) {
            int r = ar0 + 32 * j;
            cpa16(sb + adst0 + 32 * j * ROWB,
                  asrc + (size_t)stok[r] * NH + k0 + ach * 8);
        }
#pragma unroll
        for (int j = 0; j < 8; j++) {
            int r = br0 + 16 * j;
            cpa16(sb + bdst0 + 16 * j * ROWB,
                  bsrc0 + wb + (size_t)r * NH + k0 + bch * 8);
        }
        CP_COMMIT();
    };

    constexpr int NC = NH / CH;   // 64
    issue(0);

#pragma unroll 1
    for (int c = 0; c < NC; c++) {
        if (c + 1 < NC) { issue(c + 1); CP_WAIT(1); }
        else CP_WAIT(0);
        __syncthreads();

        uint32_t sb = su + 1024 + (c & 1) * STG1;
#pragma unroll
        for (int kk = 0; kk < 2; kk++) {
            uint32_t ao = sb + (wM * 32 + (lane & 15)) * ROWB + (lane >> 4) * 16 + kk * 32;
            uint32_t bo = sb + 2 * APL + (wN * 32 + (lane & 15)) * ROWB + (lane >> 4) * 16 + kk * 32;
            uint32_t ah[2][4], al[2][4];
#pragma unroll
            for (int mf = 0; mf < 2; mf++) {
                ldm4(ah[mf], ao + mf * 16 * ROWB);
                ldm4(al[mf], ao + APL + mf * 16 * ROWB);
            }
            {   // w1
                uint32_t bh[2][4], bl[2][4];
#pragma unroll
                for (int g = 0; g < 2; g++) {
                    ldm4(bh[g], bo + g * 16 * ROWB);
                    ldm4(bl[g], bo + BPL + g * 16 * ROWB);
                }
#pragma unroll
                for (int mf = 0; mf < 2; mf++)
#pragma unroll
                    for (int nf = 0; nf < 4; nf++) {
                        int g = nf >> 1, o = nf & 1;
                        mma16816(C1[mf][nf], ah[mf], bh[g][o], bh[g][o + 2]);
                        mma16816(C1[mf][nf], ah[mf], bl[g][o], bl[g][o + 2]);
                        mma16816(C1[mf][nf], al[mf], bh[g][o], bh[g][o + 2]);
                    }
            }
            {   // w3 (reuse A frags)
                uint32_t bh[2][4], bl[2][4];
#pragma unroll
                for (int g = 0; g < 2; g++) {
                    ldm4(bh[g], bo + 2 * BPL + g * 16 * ROWB);
                    ldm4(bl[g], bo + 3 * BPL + g * 16 * ROWB);
                }
#pragma unroll
                for (int mf = 0; mf < 2; mf++)
#pragma unroll
                    for (int nf = 0; nf < 4; nf++) {
                        int g = nf >> 1, o = nf & 1;
                        mma16816(C3[mf][nf], ah[mf], bh[g][o], bh[g][o + 2]);
                        mma16816(C3[mf][nf], ah[mf], bl[g][o], bl[g][o + 2]);
                        mma16816(C3[mf][nf], al[mf], bh[g][o], bh[g][o + 2]);
                    }
            }
        }
        __syncthreads();
    }

    // Epilogue: h = silu(c1)*c3*wgt, pre-split to hi/lo bf16 planes
#pragma unroll
    for (int mf = 0; mf < 2; mf++)
#pragma unroll
        for (int nf = 0; nf < 4; nf++) {
            int rb = m0 + wM * 32 + mf * 16 + (lane >> 2);
            int cc = n0 + wN * 32 + nf * 8 + (lane & 3) * 2;
#pragma unroll
            for (int hf = 0; hf < 2; hf++) {
                int r = rb + hf * 8;
                if (r < cnt) {
                    float wg = g_wgt[e * NT + r];
                    float a0 = C1[mf][nf][hf * 2], a1 = C1[mf][nf][hf * 2 + 1];
                    float h0 = a0 / (1.f + expf(-a0)) * C3[mf][nf][hf * 2] * wg;
                    float h1 = a1 / (1.f + expf(-a1)) * C3[mf][nf][hf * 2 + 1] * wg;
                    size_t off = (size_t)(e * NT + r) * NF + cc;
                    uint32_t b0 = __float_as_uint(h0), b1 = __float_as_uint(h1);
                    *(uint32_t*)(g_hh + off) = __byte_perm(b0, b1, 0x7632);
                    float l0 = h0 - __uint_as_float(b0 & 0xFFFF0000u);
                    float l1 = h1 - __uint_as_float(b1 & 0xFFFF0000u);
                    *(uint32_t*)(g_hl + off) = cvt2bf(l0, l1);
                }
            }
        }
}

// ---------------------------------------------------------------------------
// k_ffn2: out[token] += h @ w2^T. CTA 64x128, 2-stage, 2 CTAs/SM.
// ---------------------------------------------------------------------------
__global__ __launch_bounds__(256, 2) void k_ffn2(float* __restrict__ out) {
    int e = blockIdx.z;
    int cnt = g_cnt[e];
    int m0 = blockIdx.y * 64;
    if (m0 >= cnt) return;
    int n0 = blockIdx.x * 128;

    extern __shared__ char sm[];
    uint32_t su = s2u(sm);
    int tid = threadIdx.x, lane = tid & 31, wid = tid >> 5;
    int wM = wid >> 2, wN = wid & 3;

    const size_t wb = ((size_t)e * NH + n0) * NF;
    const size_t hb = (size_t)e * NT * NF;

    int ap_ = tid & 1, ach = (tid >> 1) & 3, ar0 = tid >> 3;        // A: r = ar0 + 32j
    int bpl = tid & 1, bch = (tid >> 1) & 3, br0 = tid >> 3;        // B: r = br0 + 32j
    const uint16_t* asrc = (ap_ ? g_hl : g_hh);
    const uint16_t* bsrc = (bpl ? g_w2l : g_w2h);
    uint32_t adst0 = ap_ * APL + ar0 * ROWB + ach * 16;
    uint32_t bdst0 = 2 * APL + bpl * BPL + br0 * ROWB + bch * 16;

    float C[2][4][4];
#pragma unroll
    for (int i = 0; i < 2; i++)
#pragma unroll
        for (int j = 0; j < 4; j++)
#pragma unroll
            for (int q = 0; q < 4; q++) C[i][j][q] = 0.f;

    auto issue = [&](int c) {
        int k0 = c * CH;
        uint32_t sb = su + (c & 1) * STG2;
#pragma unroll
        for (int j = 0; j < 2; j++) {
            int r = m0 + ar0 + 32 * j;
            if (r >= cnt) r = cnt - 1;
            cpa16(sb + adst0 + 32 * j * ROWB,
                  asrc + hb + (size_t)r * NF + k0 + ach * 8);
        }
#pragma unroll
        for (int j = 0; j < 4; j++) {
            int r = br0 + 32 * j;
            cpa16(sb + bdst0 + 32 * j * ROWB,
                  bsrc + wb + (size_t)r * NF + k0 + bch * 8);
        }
        CP_COMMIT();
    };

    constexpr int NC = NF / CH;   // 40
    issue(0);

#pragma unroll 1
    for (int c = 0; c < NC; c++) {
        if (c + 1 < NC) { issue(c + 1); CP_WAIT(1); }
        else CP_WAIT(0);
        __syncthreads();

        uint32_t sb = su + (c & 1) * STG2;
#pragma unroll
        for (int kk = 0; kk < 2; kk++) {
            uint32_t ao = sb + (wM * 32 + (lane & 15)) * ROWB + (lane >> 4) * 16 + kk * 32;
            uint32_t bo = sb + 2 * APL + (wN * 32 + (lane & 15)) * ROWB + (lane >> 4) * 16 + kk * 32;
            uint32_t ah[2][4], al[2][4], bh[2][4], bl[2][4];
#pragma unroll
            for (int mf = 0; mf < 2; mf++) {
                ldm4(ah[mf], ao + mf * 16 * ROWB);
                ldm4(al[mf], ao + APL + mf * 16 * ROWB);
            }
#pragma unroll
            for (int g = 0; g < 2; g++) {
                ldm4(bh[g], bo + g * 16 * ROWB);
                ldm4(bl[g], bo + BPL + g * 16 * ROWB);
            }
#pragma unroll
            for (int mf = 0; mf < 2; mf++)
#pragma unroll
                for (int nf = 0; nf < 4; nf++) {
                    int g = nf >> 1, o = nf & 1;
                    mma16816(C[mf][nf], ah[mf], bh[g][o], bh[g][o + 2]);
                    mma16816(C[mf][nf], ah[mf], bl[g][o], bl[g][o + 2]);
                    mma16816(C[mf][nf], al[mf], bh[g][o], bh[g][o + 2]);
                }
        }
        __syncthreads();
    }

    // Epilogue: scatter-accumulate (2 commutative fp32 adds/elem -> deterministic)
#pragma unroll
    for (int mf = 0; mf < 2; mf++)
#pragma unroll
        for (int nf = 0; nf < 4; nf++) {
            int rb = m0 + wM * 32 + mf * 16 + (lane >> 2);
            int cc = n0 + wN * 32 + nf * 8 + (lane & 3) * 2;
#pragma unroll
            for (int hf = 0; hf < 2; hf++) {
                int r = rb + hf * 8;
                if (r < cnt) {
                    int tok = g_tok[e * NT + r];
                    float* p = out + (size_t)tok * NH + cc;
                    atomicAdd(p + 0, C[mf][nf][hf * 2 + 0]);
                    atomicAdd(p + 1, C[mf][nf][hf * 2 + 1]);
                }
            }
        }
}

// ---------------------------------------------------------------------------
// kernel_launch
// ---------------------------------------------------------------------------
extern "C" void kernel_launch(void* const* d_in, const int* in_sizes, int n_in,
                              void* d_out, int out_size) {
    const float* x  = (const float*)d_in[0];
    const float* gw = (const float*)d_in[1];
    const float* w1 = (const float*)d_in[2];
    const float* w2 = (const float*)d_in[3];
    const float* w3 = (const float*)d_in[4];
    float* out = (float*)d_out;
    (void)in_sizes; (void)n_in;

    static bool attr_set = false;
    if (!attr_set) {
        cudaFuncSetAttribute(k_ffn1, cudaFuncAttributeMaxDynamicSharedMemorySize, SMEM1);
        cudaFuncSetAttribute(k_ffn2, cudaFuncAttributeMaxDynamicSharedMemorySize, SMEM2);
        attr_set = true;
    }

    int n4 = out_size / 4;
    k_init<<<(n4 + 255) / 256, 256>>>(out, n4);

    int nw4 = NE * NF * NH / 4;
    int nx4 = NT * NH / 4;
    k_split<0><<<(nw4 + 255) / 256, 256>>>((const float4*)w1, nw4);
    k_split<1><<<(nw4 + 255) / 256, 256>>>((const float4*)w3, nw4);
    k_split<2><<<(nw4 + 255) / 256, 256>>>((const float4*)w2, nw4);
    k_split<3><<<(nx4 + 255) / 256, 256>>>((const float4*)x, nx4);

    k_route<<<(NT * 32 + 127) / 128, 128>>>(x, gw);

    dim3 g1(NF / 128, NT / 64, NE);    // (10, 64, 12)
    k_ffn1<<<g1, 256, SMEM1>>>();

    dim3 g2(NH / 128, NT / 64, NE);    // (16, 64, 12)
    k_ffn2<<<g2, 256, SMEM2>>>(out);
}